// round 12
// baseline (speedup 1.0000x reference)
#include <cuda_runtime.h>
#include <math.h>

#define NCELL 512
#define C 32
#define NREP 32           // counter replicas per cell (replica = point_idx & 31)
#define CAP32 64          // slots per (cell, replica); mean ~30.5
#define SCAP 1280         // smem record capacity per bin; mean ~977, +9.7 sigma

// -------- static scratch (no cudaMalloc allowed) --------
__device__ int   g_cnt32[NCELL * NREP];
__device__ int4  g_rec32[NCELL * NREP * CAP32];   // {idx, fx, fy, fz}
__device__ float g_img[NCELL * C];
__device__ float g_h1 [NCELL * C];
__device__ float g_t  [NCELL * C];
__device__ float g_out[NCELL * C];
__device__ float g_B  [NCELL * C];

// -------- zero counters + accumulated buffers --------
__global__ void zero_k() {
    int j = blockIdx.x * 256 + threadIdx.x;          // 16384 threads
    g_cnt32[j] = 0;
    g_img[j] = 0.f; g_h1[j] = 0.f; g_t[j] = 0.f; g_out[j] = 0.f;
}

// -------- bin points (R8 measured-best config: 1 point/thread) --------
__global__ void bin_k(const float* __restrict__ pos, int N) {
    int p = blockIdx.x * 256 + threadIdx.x;
    if (p >= N) return;
    float sx = pos[3 * p + 0] * 8.f;
    float sy = pos[3 * p + 1] * 8.f;
    float sz = pos[3 * p + 2] * 8.f;
    float bx = floorf(sx), by = floorf(sy), bz = floorf(sz);
    int cell = ((((int)bx) & 7) << 6) | ((((int)by) & 7) << 3) | (((int)bz) & 7);
    int r = p & (NREP - 1);
    int slot = atomicAdd(&g_cnt32[cell * NREP + r], 1);
    if (slot < CAP32) {
        int4 rec;
        rec.x = p;
        rec.y = __float_as_int(sx - bx);
        rec.z = __float_as_int(sy - by);
        rec.w = __float_as_int(sz - bz);
        g_rec32[(cell * NREP + r) * CAP32 + slot] = rec;
    }
}

#define ACC(rc, fc) { \
    float fx = __int_as_float((rc).y), fy = __int_as_float((rc).z), fz = __int_as_float((rc).w); \
    float gx = 1.f - fx, gy = 1.f - fy, gz = 1.f - fz; \
    float w00 = gy * gz, w01 = gy * fz, w10 = fy * gz, w11 = fy * fz; \
    float p0 = gx * (fc), p1 = fx * (fc); \
    a0 += w00 * p0; a1 += w01 * p0; a2 += w10 * p0; a3 += w11 * p0; \
    a4 += w00 * p1; a5 += w01 * p1; a6 += w10 * p1; a7 += w11 * p1; }

// -------- scatter (R9 protected config): 1 CTA/bin, 16 warps, smem-staged
//          records, 4-deep feat ring --------
__global__ void __launch_bounds__(512) scatter_k(const float* __restrict__ feat) {
    __shared__ int4  s_rec[SCAP];
    __shared__ int   s_pref[NREP + 1];
    __shared__ float s_all[16][8][32];

    const int b    = blockIdx.x;
    const int w    = threadIdx.x >> 5;               // 0..15
    const int lane = threadIdx.x & 31;

    // warp 0: exclusive prefix over the 32 replica counts
    if (threadIdx.x < 32) {
        int c = g_cnt32[b * NREP + lane];
        if (c > CAP32) c = CAP32;
        int x = c;
        #pragma unroll
        for (int d = 1; d < 32; d <<= 1) {
            int y = __shfl_up_sync(0xffffffffu, x, d);
            if (lane >= d) x += y;
        }
        s_pref[lane + 1] = x;
        if (lane == 0) s_pref[0] = 0;
    }
    __syncthreads();

    // cooperative compaction: replica regions -> contiguous smem list
    #pragma unroll
    for (int r = w; r < NREP; r += 16) {
        int base = s_pref[r];
        int c    = s_pref[r + 1] - base;
        const int4* src = g_rec32 + (b * NREP + r) * CAP32;
        for (int t = lane; t < c; t += 32) {
            int d = base + t;
            if (d < SCAP) s_rec[d] = __ldg(src + t);
        }
    }
    __syncthreads();

    int T = s_pref[NREP];
    if (T > SCAP) T = SCAP;

    // per-warp accumulation, feat loads pipelined 4 deep (stride 16 warps)
    float a0=0,a1=0,a2=0,a3=0,a4=0,a5=0,a6=0,a7=0;
    float F[4];
    #pragma unroll
    for (int t = 0; t < 4; t++) {
        int j = w + t * 16;
        F[t] = (j < T) ? __ldg(feat + s_rec[j].x * C + lane) : 0.f;
    }
    int k = 0;
    for (int j = w; j < T; j += 16, k++) {
        int t = k & 3;
        int4 rc = s_rec[j];                          // broadcast LDS.128
        float fc = F[t];
        int jn = j + 64;
        F[t] = (jn < T) ? __ldg(feat + s_rec[jn].x * C + lane) : 0.f;
        ACC(rc, fc);
    }

    // reduce 16 warps x 8 corners: warp w sums its half of sources for corner w&7
    s_all[w][0][lane] = a0; s_all[w][1][lane] = a1;
    s_all[w][2][lane] = a2; s_all[w][3][lane] = a3;
    s_all[w][4][lane] = a4; s_all[w][5][lane] = a5;
    s_all[w][6][lane] = a6; s_all[w][7][lane] = a7;
    __syncthreads();

    int cn = w & 7;
    int qb = (w >> 3) * 8;
    float s = 0.f;
    #pragma unroll
    for (int q = 0; q < 8; q++) s += s_all[qb + q][cn][lane];
    int bx = b >> 6, by = (b >> 3) & 7, bz = b & 7;
    int cx = (bx + (cn >> 2)) & 7;
    int cy = (by + ((cn >> 1) & 1)) & 7;
    int cz = (bz + (cn & 1)) & 7;
    atomicAdd(&g_img[((cx << 6) | (cy << 3) | cz) * C + lane], s);
}

// -------- periodic 3x3x3 conv: grid = 27 taps x 32 cell-groups (16 cells each) --------
// stage 0: img->h1 (encoder); stage 1: h1->t (inner);
// stage 2: decoder, staging computes h2 = h1 + silu(t) on the fly
__global__ void conv_k(const float* __restrict__ kern, int stage) {
    const float* src = (stage == 0) ? g_img : g_h1;
    float*       dst = (stage == 0) ? g_h1  : (stage == 1) ? g_t : g_out;

    __shared__ float s_in[16 * 32];
    const int tid = threadIdx.x;
    const int o = tid & 31, w = tid >> 5;
    const int tap = blockIdx.x % 27;
    const int grp = blockIdx.x / 27;                  // 0..31
    const int dx = tap / 9 - 1, dy = (tap / 3) % 3 - 1, dz = tap % 3 - 1;
    const int x = grp >> 2, yq = (grp & 3) << 1;      // 2 y-rows per group
    const int sx = (x + dx) & 7;

    #pragma unroll
    for (int k = 0; k < 2; k++) {
        int lc = w * 2 + k;                           // 0..15 local cell
        int y = yq + (lc >> 3), z = lc & 7;
        int si = ((sx << 6) | (((y + dy) & 7) << 3) | ((z + dz) & 7)) * 32 + o;
        float v;
        if (stage == 2) {
            float t = __ldg(&g_t[si]);
            v = __ldg(&g_h1[si]) + t * (1.f / (1.f + __expf(-t)));
        } else {
            v = __ldg(&src[si]);
        }
        s_in[lc * 32 + o] = v;
    }
    float4 kv[8];
    const float4* kp = reinterpret_cast<const float4*>(kern + (tap * 32 + o) * 32);
    #pragma unroll
    for (int i = 0; i < 8; i++) kv[i] = __ldg(&kp[i]);
    __syncthreads();

    float acc[2] = {0, 0};
    #pragma unroll
    for (int i4 = 0; i4 < 8; i4++) {
        #pragma unroll
        for (int k = 0; k < 2; k++) {
            float4 sv = *reinterpret_cast<const float4*>(&s_in[(w * 2 + k) * 32 + i4 * 4]);
            acc[k] += sv.x * kv[i4].x + sv.y * kv[i4].y
                    + sv.z * kv[i4].z + sv.w * kv[i4].w;
        }
    }
    #pragma unroll
    for (int k = 0; k < 2; k++) {
        int lc = w * 2 + k;
        int y = yq + (lc >> 3), z = lc & 7;
        int cell = (x << 6) | (y << 3) | z;
        atomicAdd(&dst[cell * 32 + o], acc[k]);
    }
}

// -------- 2x2x2 periodic box-sum of decoder output --------
__global__ void box_k() {
    int j = blockIdx.x * 256 + threadIdx.x;
    if (j >= NCELL * C) return;
    int o = j & 31, cell = j >> 5;
    int x = cell >> 6, y = (cell >> 3) & 7, z = cell & 7;
    float s = 0.f;
    #pragma unroll
    for (int k = 0; k < 8; k++) {
        int cx = (x + (k >> 2)) & 7;
        int cy = (y + ((k >> 1) & 1)) & 7;
        int cz = (z + (k & 1)) & 7;
        s += g_out[(((cx << 6) | (cy << 3) | cz) << 5) + o];
    }
    g_B[j] = s;
}

// -------- gather: recompute cell from pos; fully coalesced --------
__global__ void gather_k(const float* __restrict__ pos, float* __restrict__ out, int N) {
    int wid  = blockIdx.x * 8 + (threadIdx.x >> 5);
    int lane = threadIdx.x & 31;
    int p0 = wid * 8;
    if (p0 >= N) return;

    float v = 0.f;
    int gi = p0 * 3 + lane;
    if (lane < 24 && gi < N * 3) v = __ldg(pos + gi);

    int k8 = lane & 7;
    float ax = __shfl_sync(0xffffffffu, v, 3 * k8);
    float ay = __shfl_sync(0xffffffffu, v, 3 * k8 + 1);
    float az = __shfl_sync(0xffffffffu, v, 3 * k8 + 2);
    int cell = ((((int)floorf(ax * 8.f)) & 7) << 6)
             | ((((int)floorf(ay * 8.f)) & 7) << 3)
             |  (((int)floorf(az * 8.f)) & 7);

    #pragma unroll
    for (int k = 0; k < 8; k++) {
        int ck = __shfl_sync(0xffffffffu, cell, k);
        float val = g_B[ck * 32 + lane];
        if (p0 + k < N) out[(p0 + k) * 32 + lane] = val;
    }
}

extern "C" void kernel_launch(void* const* d_in, const int* in_sizes, int n_in,
                              void* d_out, int out_size) {
    const float* pos  = (const float*)d_in[0];
    const float* feat = (const float*)d_in[1];
    const float* enc  = (const float*)d_in[2];
    const float* inn  = (const float*)d_in[3];
    const float* dec  = (const float*)d_in[4];
    float* out = (float*)d_out;
    int N = in_sizes[0] / 3;

    zero_k   <<<64, 256>>>();                          // idx 0
    bin_k    <<<(N + 255) / 256, 256>>>(pos, N);       // idx 1
    scatter_k<<<NCELL, 512>>>(feat);                   // idx 2
    conv_k   <<<864, 256>>>(enc, 0);                   // idx 3  <-- profiled slot
    conv_k   <<<864, 256>>>(inn, 1);                   // idx 4
    conv_k   <<<864, 256>>>(dec, 2);                   // idx 5 (silu fused)
    box_k    <<<64, 256>>>();                          // idx 6
    gather_k <<<(N + 63) / 64, 256>>>(pos, out, N);    // idx 7
}

// round 13
// speedup vs baseline: 1.1343x; 1.1343x over previous
#include <cuda_runtime.h>
#include <math.h>

#define NCELL 512
#define C 32
#define NREP 32           // counter replicas per cell (replica = point_idx & 31)
#define CAP32 64          // slots per (cell, replica); mean ~30.5
#define SCAP 1280         // smem record capacity per bin; mean ~977, +9.7 sigma

// -------- static scratch (no cudaMalloc allowed) --------
__device__ int   g_cnt32[NCELL * NREP];
__device__ int4  g_rec32[NCELL * NREP * CAP32];   // {idx, fx, fy, fz}
__device__ float g_img[NCELL * C];
__device__ float g_h1 [NCELL * C];
__device__ float g_t  [NCELL * C];
__device__ float g_out[NCELL * C];
__device__ float g_B  [NCELL * C];
__device__ int   g_pad[32];

// -------- zero counters + accumulated buffers --------
__global__ void zero_k() {
    int j = blockIdx.x * 256 + threadIdx.x;          // 16384 threads
    g_cnt32[j] = 0;
    g_img[j] = 0.f; g_h1[j] = 0.f; g_t[j] = 0.f; g_out[j] = 0.f;
}

// -------- probe: keeps scatter_k in ncu's profiled slot (4th launch) --------
__global__ void probe_k() {
    if (threadIdx.x == 0) g_pad[0] = 1;
}

// -------- bin points (R8 measured-best config: 1 point/thread) --------
__global__ void bin_k(const float* __restrict__ pos, int N) {
    int p = blockIdx.x * 256 + threadIdx.x;
    if (p >= N) return;
    float sx = pos[3 * p + 0] * 8.f;
    float sy = pos[3 * p + 1] * 8.f;
    float sz = pos[3 * p + 2] * 8.f;
    float bx = floorf(sx), by = floorf(sy), bz = floorf(sz);
    int cell = ((((int)bx) & 7) << 6) | ((((int)by) & 7) << 3) | (((int)bz) & 7);
    int r = p & (NREP - 1);
    int slot = atomicAdd(&g_cnt32[cell * NREP + r], 1);
    if (slot < CAP32) {
        int4 rec;
        rec.x = p;
        rec.y = __float_as_int(sx - bx);
        rec.z = __float_as_int(sy - by);
        rec.w = __float_as_int(sz - bz);
        g_rec32[(cell * NREP + r) * CAP32 + slot] = rec;
    }
}

#define ACC(rc, fc) { \
    float fx = __int_as_float((rc).y), fy = __int_as_float((rc).z), fz = __int_as_float((rc).w); \
    float gx = 1.f - fx, gy = 1.f - fy, gz = 1.f - fz; \
    float w00 = gy * gz, w01 = gy * fz, w10 = fy * gz, w11 = fy * fz; \
    float p0 = gx * (fc), p1 = fx * (fc); \
    a0 += w00 * p0; a1 += w01 * p0; a2 += w10 * p0; a3 += w11 * p0; \
    a4 += w00 * p1; a5 += w01 * p1; a6 += w10 * p1; a7 += w11 * p1; }

// -------- scatter: 1 CTA/bin, 16 warps, smem-staged records + 64 padding
//          records (guard-free 4-deep feat prefetch), unroll-4 hot loop --------
__global__ void __launch_bounds__(512) scatter_k(const float* __restrict__ feat) {
    __shared__ int4  s_rec[SCAP + 64];
    __shared__ int   s_pref[NREP + 1];
    __shared__ float s_all[16][8][32];

    const int b    = blockIdx.x;
    const int w    = threadIdx.x >> 5;               // 0..15
    const int lane = threadIdx.x & 31;

    // warp 0: exclusive prefix over the 32 replica counts
    if (threadIdx.x < 32) {
        int c = g_cnt32[b * NREP + lane];
        if (c > CAP32) c = CAP32;
        int x = c;
        #pragma unroll
        for (int d = 1; d < 32; d <<= 1) {
            int y = __shfl_up_sync(0xffffffffu, x, d);
            if (lane >= d) x += y;
        }
        s_pref[lane + 1] = x;
        if (lane == 0) s_pref[0] = 0;
    }
    __syncthreads();

    // cooperative compaction: replica regions -> contiguous smem list
    #pragma unroll
    for (int r = w; r < NREP; r += 16) {
        int base = s_pref[r];
        int c    = s_pref[r + 1] - base;
        const int4* src = g_rec32 + (b * NREP + r) * CAP32;
        for (int t = lane; t < c; t += 32) {
            int d = base + t;
            if (d < SCAP) s_rec[d] = __ldg(src + t);
        }
    }
    // pad 64 dummy records past T so prefetch needs no bounds check
    {
        int Tt = s_pref[NREP]; if (Tt > SCAP) Tt = SCAP;
        if (threadIdx.x < 64) s_rec[Tt + threadIdx.x] = make_int4(0, 0, 0, 0);
    }
    __syncthreads();

    int T = s_pref[NREP];
    if (T > SCAP) T = SCAP;

    // per-warp accumulation, feat loads pipelined 4 deep (stride 16 warps)
    float a0=0,a1=0,a2=0,a3=0,a4=0,a5=0,a6=0,a7=0;
    float F[4];
    #pragma unroll
    for (int t = 0; t < 4; t++)
        F[t] = __ldg(feat + s_rec[w + t * 16].x * C + lane);   // padded: always safe

    int k = 0;
    #pragma unroll 4
    for (int j = w; j < T; j += 16, k++) {
        int t = k & 3;
        int4 rc = s_rec[j];                          // broadcast LDS.128
        float fc = F[t];
        F[t] = __ldg(feat + s_rec[j + 64].x * C + lane);       // guard-free prefetch
        ACC(rc, fc);
    }

    // reduce 16 warps x 8 corners: warp w sums its half of sources for corner w&7
    s_all[w][0][lane] = a0; s_all[w][1][lane] = a1;
    s_all[w][2][lane] = a2; s_all[w][3][lane] = a3;
    s_all[w][4][lane] = a4; s_all[w][5][lane] = a5;
    s_all[w][6][lane] = a6; s_all[w][7][lane] = a7;
    __syncthreads();

    int cn = w & 7;
    int qb = (w >> 3) * 8;
    float s = 0.f;
    #pragma unroll
    for (int q = 0; q < 8; q++) s += s_all[qb + q][cn][lane];
    int bx = b >> 6, by = (b >> 3) & 7, bz = b & 7;
    int cx = (bx + (cn >> 2)) & 7;
    int cy = (by + ((cn >> 1) & 1)) & 7;
    int cz = (bz + (cn & 1)) & 7;
    atomicAdd(&g_img[((cx << 6) | (cy << 3) | cz) * C + lane], s);
}

// -------- periodic 3x3x3 conv: grid = 27 taps x 16 half-slabs (R11 config) --------
// stage 0: img->h1 (encoder); stage 1: h1->t (inner);
// stage 2: decoder, staging computes h2 = h1 + silu(t) on the fly
__global__ void conv_k(const float* __restrict__ kern, int stage) {
    const float* src = (stage == 0) ? g_img : g_h1;
    float*       dst = (stage == 0) ? g_h1  : (stage == 1) ? g_t : g_out;

    __shared__ float s_in[32 * 32];
    const int tid = threadIdx.x;
    const int o = tid & 31, w = tid >> 5;
    const int tap = blockIdx.x % 27;
    const int grp = blockIdx.x / 27;
    const int dx = tap / 9 - 1, dy = (tap / 3) % 3 - 1, dz = tap % 3 - 1;
    const int x = grp >> 1, yh = (grp & 1) << 2;
    const int sx = (x + dx) & 7;

    #pragma unroll
    for (int k = 0; k < 4; k++) {
        int lc = w * 4 + k;
        int y = yh + (lc >> 3), z = lc & 7;
        int si = ((sx << 6) | (((y + dy) & 7) << 3) | ((z + dz) & 7)) * 32 + o;
        float v;
        if (stage == 2) {
            float t = __ldg(&g_t[si]);
            v = __ldg(&g_h1[si]) + t * (1.f / (1.f + __expf(-t)));
        } else {
            v = __ldg(&src[si]);
        }
        s_in[lc * 32 + o] = v;
    }
    float4 kv[8];
    const float4* kp = reinterpret_cast<const float4*>(kern + (tap * 32 + o) * 32);
    #pragma unroll
    for (int i = 0; i < 8; i++) kv[i] = __ldg(&kp[i]);
    __syncthreads();

    float acc[4] = {0,0,0,0};
    #pragma unroll
    for (int i4 = 0; i4 < 8; i4++) {
        #pragma unroll
        for (int k = 0; k < 4; k++) {
            float4 sv = *reinterpret_cast<const float4*>(&s_in[(w * 4 + k) * 32 + i4 * 4]);
            acc[k] += sv.x * kv[i4].x + sv.y * kv[i4].y
                    + sv.z * kv[i4].z + sv.w * kv[i4].w;
        }
    }
    int base = (grp * 32 + w * 4) * 32 + o;
    #pragma unroll
    for (int k = 0; k < 4; k++)
        atomicAdd(&dst[base + k * 32], acc[k]);
}

// -------- 2x2x2 periodic box-sum of decoder output --------
__global__ void box_k() {
    int j = blockIdx.x * 256 + threadIdx.x;
    if (j >= NCELL * C) return;
    int o = j & 31, cell = j >> 5;
    int x = cell >> 6, y = (cell >> 3) & 7, z = cell & 7;
    float s = 0.f;
    #pragma unroll
    for (int k = 0; k < 8; k++) {
        int cx = (x + (k >> 2)) & 7;
        int cy = (y + ((k >> 1) & 1)) & 7;
        int cz = (z + (k & 1)) & 7;
        s += g_out[(((cx << 6) | (cy << 3) | cz) << 5) + o];
    }
    g_B[j] = s;
}

// -------- gather: recompute cell from pos; fully coalesced --------
__global__ void gather_k(const float* __restrict__ pos, float* __restrict__ out, int N) {
    int wid  = blockIdx.x * 8 + (threadIdx.x >> 5);
    int lane = threadIdx.x & 31;
    int p0 = wid * 8;
    if (p0 >= N) return;

    float v = 0.f;
    int gi = p0 * 3 + lane;
    if (lane < 24 && gi < N * 3) v = __ldg(pos + gi);

    int k8 = lane & 7;
    float ax = __shfl_sync(0xffffffffu, v, 3 * k8);
    float ay = __shfl_sync(0xffffffffu, v, 3 * k8 + 1);
    float az = __shfl_sync(0xffffffffu, v, 3 * k8 + 2);
    int cell = ((((int)floorf(ax * 8.f)) & 7) << 6)
             | ((((int)floorf(ay * 8.f)) & 7) << 3)
             |  (((int)floorf(az * 8.f)) & 7);

    #pragma unroll
    for (int k = 0; k < 8; k++) {
        int ck = __shfl_sync(0xffffffffu, cell, k);
        float val = g_B[ck * 32 + lane];
        if (p0 + k < N) out[(p0 + k) * 32 + lane] = val;
    }
}

extern "C" void kernel_launch(void* const* d_in, const int* in_sizes, int n_in,
                              void* d_out, int out_size) {
    const float* pos  = (const float*)d_in[0];
    const float* feat = (const float*)d_in[1];
    const float* enc  = (const float*)d_in[2];
    const float* inn  = (const float*)d_in[3];
    const float* dec  = (const float*)d_in[4];
    float* out = (float*)d_out;
    int N = in_sizes[0] / 3;

    zero_k   <<<64, 256>>>();                          // idx 0
    bin_k    <<<(N + 255) / 256, 256>>>(pos, N);       // idx 1
    probe_k  <<<1, 32>>>();                            // idx 2
    scatter_k<<<NCELL, 512>>>(feat);                   // idx 3  <-- profiled slot
    conv_k   <<<432, 256>>>(enc, 0);                   // idx 4
    conv_k   <<<432, 256>>>(inn, 1);                   // idx 5
    conv_k   <<<432, 256>>>(dec, 2);                   // idx 6 (silu fused)
    box_k    <<<64, 256>>>();                          // idx 7
    gather_k <<<(N + 63) / 64, 256>>>(pos, out, N);    // idx 8
}

// round 14
// speedup vs baseline: 1.2410x; 1.0941x over previous
#include <cuda_runtime.h>
#include <math.h>

#define NCELL 512
#define C 32
#define NREP 32           // counter replicas per cell (replica = point_idx & 31)
#define CAP32 64          // slots per (cell, replica); mean ~30.5
#define SCAP 1280         // smem record capacity per bin; mean ~977, +9.7 sigma
#define KT_STAGE 27648    // 27*32*32 per conv stage

// -------- static scratch (no cudaMalloc allowed) --------
__device__ int   g_cnt32[NCELL * NREP];
__device__ int4  g_rec32[NCELL * NREP * CAP32];   // {idx, fx, fy, fz}
__device__ float g_img[NCELL * C];
__device__ float g_h1 [NCELL * C];
__device__ float g_t  [NCELL * C];
__device__ float g_out[NCELL * C];
__device__ float g_B  [NCELL * C];
__device__ float g_kt [3 * KT_STAGE];             // transposed kernels [stage][tap][i][o]

// -------- zero counters/buffers + transpose conv kernels to [tap][i][o] --------
__global__ void zero_k(const float* __restrict__ enc, const float* __restrict__ inn,
                       const float* __restrict__ dec) {
    int j = blockIdx.x * 256 + threadIdx.x;          // grid 384 -> 98304 threads
    if (j < NCELL * NREP) g_cnt32[j] = 0;
    if (j < NCELL * C) {
        g_img[j] = 0.f; g_h1[j] = 0.f; g_t[j] = 0.f; g_out[j] = 0.f;
    }
    if (j < KT_STAGE) {                               // one element per stage per thread
        int tap = j >> 10, rem = j & 1023;
        int i = rem >> 5, o = rem & 31;
        int src = (tap * 32 + o) * 32 + i;            // original [tap][o][i]
        g_kt[j]                = __ldg(&enc[src]);
        g_kt[KT_STAGE + j]     = __ldg(&inn[src]);
        g_kt[2 * KT_STAGE + j] = __ldg(&dec[src]);
    }
}

// -------- bin points (R8 measured-best config: 1 point/thread) --------
__global__ void bin_k(const float* __restrict__ pos, int N) {
    int p = blockIdx.x * 256 + threadIdx.x;
    if (p >= N) return;
    float sx = pos[3 * p + 0] * 8.f;
    float sy = pos[3 * p + 1] * 8.f;
    float sz = pos[3 * p + 2] * 8.f;
    float bx = floorf(sx), by = floorf(sy), bz = floorf(sz);
    int cell = ((((int)bx) & 7) << 6) | ((((int)by) & 7) << 3) | (((int)bz) & 7);
    int r = p & (NREP - 1);
    int slot = atomicAdd(&g_cnt32[cell * NREP + r], 1);
    if (slot < CAP32) {
        int4 rec;
        rec.x = p;
        rec.y = __float_as_int(sx - bx);
        rec.z = __float_as_int(sy - by);
        rec.w = __float_as_int(sz - bz);
        g_rec32[(cell * NREP + r) * CAP32 + slot] = rec;
    }
}

#define ACC(rc, fc) { \
    float fx = __int_as_float((rc).y), fy = __int_as_float((rc).z), fz = __int_as_float((rc).w); \
    float gx = 1.f - fx, gy = 1.f - fy, gz = 1.f - fz; \
    float w00 = gy * gz, w01 = gy * fz, w10 = fy * gz, w11 = fy * fz; \
    float p0 = gx * (fc), p1 = fx * (fc); \
    a0 += w00 * p0; a1 += w01 * p0; a2 += w10 * p0; a3 += w11 * p0; \
    a4 += w00 * p1; a5 += w01 * p1; a6 += w10 * p1; a7 += w11 * p1; }

// -------- scatter (R13 protected): 1 CTA/bin, 16 warps, padded smem records,
//          guard-free 4-deep feat prefetch, unroll-4 --------
__global__ void __launch_bounds__(512) scatter_k(const float* __restrict__ feat) {
    __shared__ int4  s_rec[SCAP + 64];
    __shared__ int   s_pref[NREP + 1];
    __shared__ float s_all[16][8][32];

    const int b    = blockIdx.x;
    const int w    = threadIdx.x >> 5;               // 0..15
    const int lane = threadIdx.x & 31;

    if (threadIdx.x < 32) {
        int c = g_cnt32[b * NREP + lane];
        if (c > CAP32) c = CAP32;
        int x = c;
        #pragma unroll
        for (int d = 1; d < 32; d <<= 1) {
            int y = __shfl_up_sync(0xffffffffu, x, d);
            if (lane >= d) x += y;
        }
        s_pref[lane + 1] = x;
        if (lane == 0) s_pref[0] = 0;
    }
    __syncthreads();

    #pragma unroll
    for (int r = w; r < NREP; r += 16) {
        int base = s_pref[r];
        int c    = s_pref[r + 1] - base;
        const int4* src = g_rec32 + (b * NREP + r) * CAP32;
        for (int t = lane; t < c; t += 32) {
            int d = base + t;
            if (d < SCAP) s_rec[d] = __ldg(src + t);
        }
    }
    {
        int Tt = s_pref[NREP]; if (Tt > SCAP) Tt = SCAP;
        if (threadIdx.x < 64) s_rec[Tt + threadIdx.x] = make_int4(0, 0, 0, 0);
    }
    __syncthreads();

    int T = s_pref[NREP];
    if (T > SCAP) T = SCAP;

    float a0=0,a1=0,a2=0,a3=0,a4=0,a5=0,a6=0,a7=0;
    float F[4];
    #pragma unroll
    for (int t = 0; t < 4; t++)
        F[t] = __ldg(feat + s_rec[w + t * 16].x * C + lane);

    int k = 0;
    #pragma unroll 4
    for (int j = w; j < T; j += 16, k++) {
        int t = k & 3;
        int4 rc = s_rec[j];
        float fc = F[t];
        F[t] = __ldg(feat + s_rec[j + 64].x * C + lane);
        ACC(rc, fc);
    }

    s_all[w][0][lane] = a0; s_all[w][1][lane] = a1;
    s_all[w][2][lane] = a2; s_all[w][3][lane] = a3;
    s_all[w][4][lane] = a4; s_all[w][5][lane] = a5;
    s_all[w][6][lane] = a6; s_all[w][7][lane] = a7;
    __syncthreads();

    int cn = w & 7;
    int qb = (w >> 3) * 8;
    float s = 0.f;
    #pragma unroll
    for (int q = 0; q < 8; q++) s += s_all[qb + q][cn][lane];
    int bx = b >> 6, by = (b >> 3) & 7, bz = b & 7;
    int cx = (bx + (cn >> 2)) & 7;
    int cy = (by + ((cn >> 1) & 1)) & 7;
    int cz = (bz + (cn & 1)) & 7;
    atomicAdd(&g_img[((cx << 6) | (cy << 3) | cz) * C + lane], s);
}

// -------- periodic 3x3x3 conv: 27 taps x 16 half-slabs; coalesced transposed
//          kernel loads (lane = out-channel contiguous) --------
// stage 0: img->h1; stage 1: h1->t; stage 2: decoder with fused h1+silu(t) staging
__global__ void conv_k(int stage) {
    const float* src = (stage == 0) ? g_img : g_h1;
    float*       dst = (stage == 0) ? g_h1  : (stage == 1) ? g_t : g_out;
    const float* kern = g_kt + stage * KT_STAGE;

    __shared__ float s_in[32 * 32];
    const int tid = threadIdx.x;
    const int o = tid & 31, w = tid >> 5;
    const int tap = blockIdx.x % 27;
    const int grp = blockIdx.x / 27;
    const int dx = tap / 9 - 1, dy = (tap / 3) % 3 - 1, dz = tap % 3 - 1;
    const int x = grp >> 1, yh = (grp & 1) << 2;
    const int sx = (x + dx) & 7;

    // coalesced weight loads: kern[tap][i][o], lane = o contiguous (1 wavefront each)
    float kv[32];
    const float* kp = kern + tap * 1024 + o;
    #pragma unroll
    for (int i = 0; i < 32; i++) kv[i] = __ldg(kp + i * 32);

    #pragma unroll
    for (int k = 0; k < 4; k++) {
        int lc = w * 4 + k;
        int y = yh + (lc >> 3), z = lc & 7;
        int si = ((sx << 6) | (((y + dy) & 7) << 3) | ((z + dz) & 7)) * 32 + o;
        float v;
        if (stage == 2) {
            float t = __ldg(&g_t[si]);
            v = __ldg(&g_h1[si]) + t * (1.f / (1.f + __expf(-t)));
        } else {
            v = __ldg(&src[si]);
        }
        s_in[lc * 32 + o] = v;
    }
    __syncthreads();

    float acc[4] = {0,0,0,0};
    #pragma unroll
    for (int i4 = 0; i4 < 8; i4++) {
        #pragma unroll
        for (int k = 0; k < 4; k++) {
            float4 sv = *reinterpret_cast<const float4*>(&s_in[(w * 4 + k) * 32 + i4 * 4]);
            acc[k] += sv.x * kv[i4 * 4 + 0] + sv.y * kv[i4 * 4 + 1]
                    + sv.z * kv[i4 * 4 + 2] + sv.w * kv[i4 * 4 + 3];
        }
    }
    int base = (grp * 32 + w * 4) * 32 + o;
    #pragma unroll
    for (int k = 0; k < 4; k++)
        atomicAdd(&dst[base + k * 32], acc[k]);
}

// -------- 2x2x2 periodic box-sum of decoder output --------
__global__ void box_k() {
    int j = blockIdx.x * 256 + threadIdx.x;
    if (j >= NCELL * C) return;
    int o = j & 31, cell = j >> 5;
    int x = cell >> 6, y = (cell >> 3) & 7, z = cell & 7;
    float s = 0.f;
    #pragma unroll
    for (int k = 0; k < 8; k++) {
        int cx = (x + (k >> 2)) & 7;
        int cy = (y + ((k >> 1) & 1)) & 7;
        int cz = (z + (k & 1)) & 7;
        s += g_out[(((cx << 6) | (cy << 3) | cz) << 5) + o];
    }
    g_B[j] = s;
}

// -------- gather: recompute cell from pos; fully coalesced --------
__global__ void gather_k(const float* __restrict__ pos, float* __restrict__ out, int N) {
    int wid  = blockIdx.x * 8 + (threadIdx.x >> 5);
    int lane = threadIdx.x & 31;
    int p0 = wid * 8;
    if (p0 >= N) return;

    float v = 0.f;
    int gi = p0 * 3 + lane;
    if (lane < 24 && gi < N * 3) v = __ldg(pos + gi);

    int k8 = lane & 7;
    float ax = __shfl_sync(0xffffffffu, v, 3 * k8);
    float ay = __shfl_sync(0xffffffffu, v, 3 * k8 + 1);
    float az = __shfl_sync(0xffffffffu, v, 3 * k8 + 2);
    int cell = ((((int)floorf(ax * 8.f)) & 7) << 6)
             | ((((int)floorf(ay * 8.f)) & 7) << 3)
             |  (((int)floorf(az * 8.f)) & 7);

    #pragma unroll
    for (int k = 0; k < 8; k++) {
        int ck = __shfl_sync(0xffffffffu, cell, k);
        float val = g_B[ck * 32 + lane];
        if (p0 + k < N) out[(p0 + k) * 32 + lane] = val;
    }
}

extern "C" void kernel_launch(void* const* d_in, const int* in_sizes, int n_in,
                              void* d_out, int out_size) {
    const float* pos  = (const float*)d_in[0];
    const float* feat = (const float*)d_in[1];
    const float* enc  = (const float*)d_in[2];
    const float* inn  = (const float*)d_in[3];
    const float* dec  = (const float*)d_in[4];
    float* out = (float*)d_out;
    int N = in_sizes[0] / 3;

    zero_k   <<<384, 256>>>(enc, inn, dec);            // idx 0 (zero + kern transpose)
    bin_k    <<<(N + 255) / 256, 256>>>(pos, N);       // idx 1
    scatter_k<<<NCELL, 512>>>(feat);                   // idx 2 (protected)
    conv_k   <<<432, 256>>>(0);                        // idx 3  <-- profiled slot
    conv_k   <<<432, 256>>>(1);                        // idx 4
    conv_k   <<<432, 256>>>(2);                        // idx 5 (silu fused)
    box_k    <<<64, 256>>>();                          // idx 6
    gather_k <<<(N + 63) / 64, 256>>>(pos, out, N);    // idx 7
}